// round 7
// baseline (speedup 1.0000x reference)
#include <cuda_runtime.h>

#define BS   16
#define DD   4096
#define NN   512
#define RR   16
#define EPSV 1e-6f
#define INVT 100.0f

#define GRID   592          // 148 SMs * 4 blocks (co-resident: regs+smem both cap at 4)
#define TPB    128
#define NSLICE 16           // P partial slices (256 d each)
#define NBTB   32           // BtB partial slices (128 d each)
#define NCTC   4

#define NU_PMAT 1024        // (b16, ds16, nc4)
#define NU_COEF 64
#define NU_QMAT 512         // (b16, dc32)
#define NU_OUT  512

// dynamic smem: bss 4096 + 2 x-tile buffers (128*33 each) = 12544 floats
#define XSBUF   4224
#define SMEM_FLOATS (4096 + 2 * XSBUF)
#define SMEM_BYTES  (SMEM_FLOATS * 4)

typedef unsigned long long u64;

// ---------------- scratch ----------------
__device__ float g_bases[BS * DD * RR];
__device__ float g_coef [BS * NN * RR];
__device__ float g_Ppart[BS * NSLICE * NN * RR];
__device__ float g_btbp [BS * NBTB * 256];
__device__ float g_ctcp [BS * NCTC * 256];

__device__ unsigned g_gen    = 0;
__device__ unsigned g_arrive = 0;
__device__ unsigned g_work   = 0;

// ---------------- packed f32x2 ----------------
__device__ __forceinline__ void ffma2(u64& acc, u64 a, u64 b) {
    asm("fma.rn.f32x2 %0, %1, %2, %3;" : "=l"(acc) : "l"(a), "l"(b), "l"(acc));
}
__device__ __forceinline__ u64 packf2(float lo, float hi) {
    u64 r; asm("mov.b64 %0, {%1, %2};" : "=l"(r) : "f"(lo), "f"(hi)); return r;
}
__device__ __forceinline__ void unpackf2(u64 v, float& lo, float& hi) {
    asm("mov.b64 {%0, %1}, %2;" : "=f"(lo), "=f"(hi) : "l"(v));
}
__device__ __forceinline__ void fma16_2(u64* acc2, u64 xv2, const float* __restrict__ row) {
    const ulonglong2* r2 = reinterpret_cast<const ulonglong2*>(row);
#pragma unroll
    for (int q = 0; q < 4; ++q) {
        ulonglong2 p = r2[q];
        ffma2(acc2[2*q+0], xv2, p.x);
        ffma2(acc2[2*q+1], xv2, p.y);
    }
}
__device__ __forceinline__ void unpack_acc(const u64* acc2, float* v) {
#pragma unroll
    for (int q = 0; q < 8; ++q) unpackf2(acc2[q], v[2*q], v[2*q+1]);
}

// ---------------- helpers ----------------
__device__ __forceinline__ void load16(const float* __restrict__ src, float* v) {
    const float4* s4 = reinterpret_cast<const float4*>(src);
#pragma unroll
    for (int q = 0; q < 4; ++q) {
        float4 t = s4[q];
        v[4*q+0] = t.x; v[4*q+1] = t.y; v[4*q+2] = t.z; v[4*q+3] = t.w;
    }
}
__device__ __forceinline__ void store16(float* __restrict__ dst, const float* v) {
    float4* d4 = reinterpret_cast<float4*>(dst);
#pragma unroll
    for (int q = 0; q < 4; ++q)
        d4[q] = make_float4(v[4*q+0], v[4*q+1], v[4*q+2], v[4*q+3]);
}
__device__ __forceinline__ void mat16(float* den, const float* v, const float* __restrict__ G) {
#pragma unroll
    for (int s2 = 0; s2 < 16; ++s2) den[s2] = 0.f;
#pragma unroll
    for (int r = 0; r < 16; ++r) {
        float c = v[r];
        const float* row = &G[r * 16];
#pragma unroll
        for (int s2 = 0; s2 < 16; ++s2) den[s2] = fmaf(c, row[s2], den[s2]);
    }
}

// ---------------- grid barrier ----------------
__device__ __forceinline__ unsigned grid_barrier(unsigned gen) {
    __threadfence();
    __syncthreads();
    if (threadIdx.x == 0) {
        unsigned a = atomicAdd(&g_arrive, 1u);
        if (a == GRID - 1u) {
            g_arrive = 0u;
            atomicExch(&g_work, 0u);
            __threadfence();
            atomicAdd(&g_gen, 1u);
        } else {
            while (*((volatile unsigned*)&g_gen) == gen) { }
        }
    }
    __syncthreads();
    __threadfence();
    return gen + 1u;
}

// ---------------- work stealing ----------------
__shared__ int sm_w;
__device__ __forceinline__ int grab() {
    __syncthreads();
    if (threadIdx.x == 0) sm_w = (int)atomicAdd(&g_work, 1u);
    __syncthreads();
    return sm_w;
}

extern __shared__ __align__(16) float smu[];

// ---------------- pmat: double-buffered smem tiles, 1 sync/tile ----------------
__device__ void pmat_phase(const float* __restrict__ x, const float* __restrict__ bsrc, bool gram) {
    const int tid = threadIdx.x;
    float* bss = smu;                         // 4096 fl: 256 d x 16 r
    float* xs0 = smu + 4096;
    float* xs1 = smu + 4096 + XSBUF;
    const int srow = tid >> 3;                // 0..15
    const int sc4  = tid & 7;                 // 0..7

    for (;;) {
        int u = grab();
        if (u >= NU_PMAT) break;
        const int nc = u & 3;
        const int ds = (u >> 2) & 15;
        const int b  = u >> 6;

        // stage bases slice
        {
            const float4* s = reinterpret_cast<const float4*>(
                bsrc + ((size_t)b * DD + (size_t)ds * 256) * RR);
            float4* d4 = reinterpret_cast<float4*>(bss);
#pragma unroll
            for (int i = 0; i < 8; ++i) d4[tid + i * 128] = s[tid + i * 128];
        }

        const float* xbase = x + ((size_t)b * NN + (size_t)nc * 128) * DD + (size_t)ds * 256;

        u64 acc2[8];
#pragma unroll
        for (int q = 0; q < 8; ++q) acc2[q] = 0ull;

        // preload tile 0
        float4 pre[8];
#pragma unroll
        for (int k = 0; k < 8; ++k)
            pre[k] = *reinterpret_cast<const float4*>(xbase + (size_t)(srow + k * 16) * DD + sc4 * 4);

        __syncthreads();   // bss ready, xs free (prev unit done)

#pragma unroll
        for (int k = 0; k < 8; ++k) {
            float* dp = xs0 + (srow + k * 16) * 33 + sc4 * 4;
            dp[0] = pre[k].x; dp[1] = pre[k].y; dp[2] = pre[k].z; dp[3] = pre[k].w;
        }
        __syncthreads();

#pragma unroll 1
        for (int t = 0; t < 8; ++t) {
            const float* cur = ((t & 1) ? xs1 : xs0) + tid * 33;
            const bool more = (t < 7);
            if (more) {
                // prefetch tile t+1 (latency hidden by compute below)
#pragma unroll
                for (int k = 0; k < 8; ++k)
                    pre[k] = *reinterpret_cast<const float4*>(
                        xbase + (size_t)(srow + k * 16) * DD + (t + 1) * 32 + sc4 * 4);
            }
#pragma unroll
            for (int j = 0; j < 32; ++j) {
                float xv = cur[j];
                fma16_2(acc2, packf2(xv, xv), &bss[(t * 32 + j) * RR]);
            }
            if (more) {
                float* nb = (t & 1) ? xs0 : xs1;
#pragma unroll
                for (int k = 0; k < 8; ++k) {
                    float* dp = nb + (srow + k * 16) * 33 + sc4 * 4;
                    dp[0] = pre[k].x; dp[1] = pre[k].y; dp[2] = pre[k].z; dp[3] = pre[k].w;
                }
                __syncthreads();
            }
        }

        float acc[16];
        unpack_acc(acc2, acc);
        const int n = nc * 128 + tid;
        store16(g_Ppart + (((size_t)b * NSLICE + ds) * NN + n) * RR, acc);

        if (gram && nc == 0) {
#pragma unroll
            for (int half = 0; half < 2; ++half) {
#pragma unroll
                for (int k = 0; k < 2; ++k) {
                    int p2 = tid + k * 128;
                    int r = p2 >> 4, s2 = p2 & 15;
                    float s = 0.f;
                    const float* base = &bss[half * 128 * 16];
#pragma unroll 8
                    for (int i = 0; i < 128; ++i)
                        s = fmaf(base[i * 16 + r], base[i * 16 + s2], s);
                    g_btbp[((size_t)b * NBTB + ds * 2 + half) * 256 + p2] = s;
                }
            }
        }
        // grab() syncs before smem reuse
    }
}

// ---------------- coef phase ----------------
__device__ void coef_phase(bool init) {
    const int tid = threadIdx.x;
    float* btbs = smu;
    float (*smcf)[17] = reinterpret_cast<float (*)[17]>(smu + 256);

    for (;;) {
        int u = grab();
        if (u >= NU_COEF) break;
        const int nc = u & 3;
        const int b  = u >> 2;

        if (tid < 64) {
            float4 s = make_float4(0.f, 0.f, 0.f, 0.f);
#pragma unroll
            for (int sl = 0; sl < NBTB; ++sl) {
                float4 v = *reinterpret_cast<const float4*>(
                    g_btbp + ((size_t)b * NBTB + sl) * 256 + tid * 4);
                s.x += v.x; s.y += v.y; s.z += v.z; s.w += v.w;
            }
            *reinterpret_cast<float4*>(&btbs[tid * 4]) = s;
        }

        const int n = nc * 128 + tid;
        float p[16];
#pragma unroll
        for (int r = 0; r < 16; ++r) p[r] = 0.f;
#pragma unroll
        for (int sl = 0; sl < NSLICE; ++sl) {
            const float4* pp = reinterpret_cast<const float4*>(
                g_Ppart + (((size_t)b * NSLICE + sl) * NN + n) * RR);
#pragma unroll
            for (int q = 0; q < 4; ++q) {
                float4 v = pp[q];
                p[4*q+0] += v.x; p[4*q+1] += v.y; p[4*q+2] += v.z; p[4*q+3] += v.w;
            }
        }

        float cf[16];
        if (init) {
            float m = p[0];
#pragma unroll
            for (int r = 1; r < 16; ++r) m = fmaxf(m, p[r]);
            float s = 0.f;
#pragma unroll
            for (int r = 0; r < 16; ++r) { cf[r] = __expf(INVT * (p[r] - m)); s += cf[r]; }
            float inv = 1.f / s;
#pragma unroll
            for (int r = 0; r < 16; ++r) cf[r] *= inv;
        } else {
            load16(g_coef + ((size_t)b * NN + n) * RR, cf);
        }
        __syncthreads();

        float den[16];
        mat16(den, cf, btbs);
#pragma unroll
        for (int r = 0; r < 16; ++r) cf[r] = cf[r] * p[r] / (den[r] + EPSV);
        store16(g_coef + ((size_t)b * NN + n) * RR, cf);

#pragma unroll
        for (int r = 0; r < 16; ++r) smcf[tid][r] = cf[r];
        __syncthreads();
#pragma unroll
        for (int k = 0; k < 2; ++k) {
            int p2 = tid + k * 128;
            int r = p2 >> 4, s2 = p2 & 15;
            float s = 0.f;
#pragma unroll 8
            for (int i = 0; i < 128; ++i) s = fmaf(smcf[i][r], smcf[i][s2], s);
            g_ctcp[((size_t)b * NCTC + nc) * 256 + p2] = s;
        }
    }
}

// ---------------- qmat: software-pipelined column loads ----------------
__device__ void qmat_phase(const float* __restrict__ x, const float* __restrict__ bold) {
    const int tid = threadIdx.x;
    float* cfs  = smu;          // 8192
    float* ctcs = smu + 8192;   // 256

    for (;;) {
        int u = grab();
        if (u >= NU_QMAT) break;
        const int dc = u & 31;
        const int b  = u >> 5;

        {
            const float4* s = reinterpret_cast<const float4*>(g_coef + (size_t)b * NN * RR);
            float4* dst = reinterpret_cast<float4*>(cfs);
#pragma unroll
            for (int i = 0; i < 16; ++i) dst[tid + i * 128] = s[tid + i * 128];
        }
        if (tid < 64) {
            float4 s = make_float4(0.f, 0.f, 0.f, 0.f);
#pragma unroll
            for (int sl = 0; sl < NCTC; ++sl) {
                float4 v = *reinterpret_cast<const float4*>(
                    g_ctcp + ((size_t)b * NCTC + sl) * 256 + tid * 4);
                s.x += v.x; s.y += v.y; s.z += v.z; s.w += v.w;
            }
            *reinterpret_cast<float4*>(&ctcs[tid * 4]) = s;
        }

        const int d = dc * 128 + tid;
        const float* xb = x + (size_t)b * NN * DD + d;

        // preload first two 8-n blocks (latency hidden under cfs staging + sync)
        float xv0[8], xv1[8];
#pragma unroll
        for (int i = 0; i < 8; ++i) xv0[i] = xb[(size_t)i * DD];
#pragma unroll
        for (int i = 0; i < 8; ++i) xv1[i] = xb[(size_t)(8 + i) * DD];

        __syncthreads();

        u64 acc2[8];
#pragma unroll
        for (int q = 0; q < 8; ++q) acc2[q] = 0ull;

#pragma unroll 1
        for (int n0 = 0; n0 < NN; n0 += 16) {
            const bool pf = (n0 + 16) < NN;
#pragma unroll
            for (int i = 0; i < 8; ++i)
                fma16_2(acc2, packf2(xv0[i], xv0[i]), &cfs[(n0 + i) * RR]);
            if (pf) {
#pragma unroll
                for (int i = 0; i < 8; ++i) xv0[i] = xb[(size_t)(n0 + 16 + i) * DD];
            }
#pragma unroll
            for (int i = 0; i < 8; ++i)
                fma16_2(acc2, packf2(xv1[i], xv1[i]), &cfs[(n0 + 8 + i) * RR]);
            if (pf) {
#pragma unroll
                for (int i = 0; i < 8; ++i) xv1[i] = xb[(size_t)(n0 + 24 + i) * DD];
            }
        }
        float acc[16];
        unpack_acc(acc2, acc);

        float bs[16];
        load16(bold + ((size_t)b * DD + d) * RR, bs);
        float den[16];
        mat16(den, bs, ctcs);
#pragma unroll
        for (int r = 0; r < 16; ++r) bs[r] = bs[r] * acc[r] / (den[r] + EPSV);
        store16(g_bases + ((size_t)b * DD + d) * RR, bs);

        __syncthreads();
        float (*smb)[17] = reinterpret_cast<float (*)[17]>(cfs);
#pragma unroll
        for (int r = 0; r < 16; ++r) smb[tid][r] = bs[r];
        __syncthreads();
#pragma unroll
        for (int k = 0; k < 2; ++k) {
            int p2 = tid + k * 128;
            int r = p2 >> 4, s2 = p2 & 15;
            float s = 0.f;
#pragma unroll 8
            for (int i = 0; i < 128; ++i) s = fmaf(smb[i][r], smb[i][s2], s);
            g_btbp[((size_t)b * NBTB + dc) * 256 + p2] = s;
        }
    }
}

// ---------------- out phase ----------------
__device__ void out_phase(float* __restrict__ out) {
    const int tid = threadIdx.x;
    float* cfs = smu;

    for (;;) {
        int u = grab();
        if (u >= NU_OUT) break;
        const int dc = u & 31;
        const int b  = u >> 5;

        {
            const float4* s = reinterpret_cast<const float4*>(g_coef + (size_t)b * NN * RR);
            float4* dst = reinterpret_cast<float4*>(cfs);
#pragma unroll
            for (int i = 0; i < 16; ++i) dst[tid + i * 128] = s[tid + i * 128];
        }
        __syncthreads();

        const int d = dc * 128 + tid;
        float bsv[16];
        load16(g_bases + ((size_t)b * DD + d) * RR, bsv);
        u64 bs2[8];
#pragma unroll
        for (int q = 0; q < 8; ++q) bs2[q] = packf2(bsv[2*q], bsv[2*q+1]);

        float* ob = out + (size_t)b * NN * DD + d;
#pragma unroll 4
        for (int n = 0; n < NN; ++n) {
            const ulonglong2* c2 = reinterpret_cast<const ulonglong2*>(&cfs[n * RR]);
            u64 o2a = 0ull, o2b = 0ull;
#pragma unroll
            for (int q = 0; q < 4; ++q) {
                ulonglong2 pq = c2[q];
                ffma2(o2a, bs2[2*q+0], pq.x);
                ffma2(o2b, bs2[2*q+1], pq.y);
            }
            float a0, a1, b0, b1;
            unpackf2(o2a, a0, a1);
            unpackf2(o2b, b0, b1);
            ob[(size_t)n * DD] = (a0 + a1) + (b0 + b1);
        }
    }
}

// ---------------- state reset ----------------
__global__ void k_reset() {
    g_gen = 0u;
    g_arrive = 0u;
    g_work = 0u;
}

// ---------------- persistent kernel ----------------
__global__ void __launch_bounds__(TPB, 4) k_all(const float* __restrict__ x,
                                                const float* __restrict__ bases_in,
                                                float* __restrict__ out) {
    unsigned gen = *((volatile unsigned*)&g_gen);

    pmat_phase(x, bases_in, true);
    gen = grid_barrier(gen);

    coef_phase(true);
    gen = grid_barrier(gen);

    for (int it = 0; it < 7; ++it) {
        qmat_phase(x, it == 0 ? bases_in : g_bases);
        gen = grid_barrier(gen);
        pmat_phase(x, g_bases, false);
        gen = grid_barrier(gen);
        coef_phase(false);
        gen = grid_barrier(gen);
    }

    out_phase(out);
}

extern "C" void kernel_launch(void* const* d_in, const int* in_sizes, int n_in,
                              void* d_out, int out_size) {
    (void)in_sizes; (void)n_in; (void)out_size;
    const float* x     = (const float*)d_in[0];
    const float* bases = (const float*)d_in[1];
    float* out = (float*)d_out;

    cudaFuncSetAttribute(k_all, cudaFuncAttributeMaxDynamicSharedMemorySize, SMEM_BYTES);

    k_reset<<<1, 1>>>();
    k_all<<<GRID, TPB, SMEM_BYTES>>>(x, bases, out);
}

// round 8
// speedup vs baseline: 1.3054x; 1.3054x over previous
#include <cuda_runtime.h>

#define BS   16
#define DD   4096
#define NN   512
#define RR   16
#define EPSV 1e-6f
#define INVT 100.0f

#define NSLICE 16     // P partial slices (256 d each)
#define NBTB   16     // BtB partial slices
#define NCTC   4      // CtC partial slices

typedef unsigned long long u64;

// ---------------- scratch ----------------
__device__ float g_bases[BS * DD * RR];
__device__ float g_coef [BS * NN * RR];
__device__ float g_Ppart[BS * NSLICE * NN * RR];   // 8 MB
__device__ float g_btbp [BS * NBTB * 256];
__device__ float g_ctcp [BS * NCTC * 256];

// ---------------- packed f32x2 ----------------
__device__ __forceinline__ void ffma2(u64& acc, u64 a, u64 b) {
    asm("fma.rn.f32x2 %0, %1, %2, %3;" : "=l"(acc) : "l"(a), "l"(b), "l"(acc));
}
__device__ __forceinline__ u64 packf2(float lo, float hi) {
    u64 r; asm("mov.b64 %0, {%1, %2};" : "=l"(r) : "f"(lo), "f"(hi)); return r;
}
__device__ __forceinline__ void unpackf2(u64 v, float& lo, float& hi) {
    asm("mov.b64 {%0, %1}, %2;" : "=f"(lo), "=f"(hi) : "l"(v));
}
// two accumulator sets share one 16-float row load
__device__ __forceinline__ void fma16_2_dual(u64* a0, u64* a1, u64 x0, u64 x1,
                                             const float* __restrict__ row) {
    const ulonglong2* r2 = reinterpret_cast<const ulonglong2*>(row);
#pragma unroll
    for (int q = 0; q < 4; ++q) {
        ulonglong2 p = r2[q];
        ffma2(a0[2*q+0], x0, p.x);
        ffma2(a0[2*q+1], x0, p.y);
        ffma2(a1[2*q+0], x1, p.x);
        ffma2(a1[2*q+1], x1, p.y);
    }
}
__device__ __forceinline__ void unpack_acc(const u64* acc2, float* v) {
#pragma unroll
    for (int q = 0; q < 8; ++q) unpackf2(acc2[q], v[2*q], v[2*q+1]);
}

// ---------------- helpers ----------------
__device__ __forceinline__ void load16(const float* __restrict__ src, float* v) {
    const float4* s4 = reinterpret_cast<const float4*>(src);
#pragma unroll
    for (int q = 0; q < 4; ++q) {
        float4 t = s4[q];
        v[4*q+0] = t.x; v[4*q+1] = t.y; v[4*q+2] = t.z; v[4*q+3] = t.w;
    }
}
__device__ __forceinline__ void store16(float* __restrict__ dst, const float* v) {
    float4* d4 = reinterpret_cast<float4*>(dst);
#pragma unroll
    for (int q = 0; q < 4; ++q)
        d4[q] = make_float4(v[4*q+0], v[4*q+1], v[4*q+2], v[4*q+3]);
}
__device__ __forceinline__ void mat16(float* den, const float* v, const float* __restrict__ G) {
#pragma unroll
    for (int s2 = 0; s2 < 16; ++s2) den[s2] = 0.f;
#pragma unroll
    for (int r = 0; r < 16; ++r) {
        float c = v[r];
        const float* row = &G[r * 16];
#pragma unroll
        for (int s2 = 0; s2 < 16; ++s2) den[s2] = fmaf(c, row[s2], den[s2]);
    }
}

// ---------------- init ----------------
__global__ void k_copy_bases(const float* __restrict__ src) {
    size_t i = (size_t)blockIdx.x * 256 + threadIdx.x;
    reinterpret_cast<float4*>(g_bases)[i] = reinterpret_cast<const float4*>(src)[i];
}

// initial BtB partials from input bases. grid (NBTB, BS), block 256 (256 d per slice)
__global__ void k_btb0(const float* __restrict__ src) {
    const int b  = blockIdx.y;
    const int sl = blockIdx.x;
    const int t  = threadIdx.x;
    const int r   = t & 15;
    const int sq  = (t >> 4) & 3;
    const int sub = t >> 6;
    const float* Ab = src + (size_t)b * DD * RR;
    float4 acc = make_float4(0.f, 0.f, 0.f, 0.f);
    const int dend = sl * 256 + 256;
    for (int d = sl * 256 + sub; d < dend; d += 4) {
        const float* row = Ab + (size_t)d * RR;
        float4 aq = *reinterpret_cast<const float4*>(row + sq * 4);
        float  ar = row[r];
        acc.x = fmaf(ar, aq.x, acc.x);
        acc.y = fmaf(ar, aq.y, acc.y);
        acc.z = fmaf(ar, aq.z, acc.z);
        acc.w = fmaf(ar, aq.w, acc.w);
    }
    __shared__ float4 red[256];
    red[t] = acc;
    __syncthreads();
    if (t < 64) {
        float4 a0 = red[t], a1 = red[t + 64], a2 = red[t + 128], a3 = red[t + 192];
        float4 s;
        s.x = a0.x + a1.x + a2.x + a3.x;
        s.y = a0.y + a1.y + a2.y + a3.y;
        s.z = a0.z + a1.z + a2.z + a3.z;
        s.w = a0.w + a1.w + a2.w + a3.w;
        int rr_ = t & 15, sq_ = t >> 4;
        *reinterpret_cast<float4*>(g_btbp + ((size_t)b * NBTB + sl) * 256 + rr_ * 16 + sq_ * 4) = s;
    }
}

// ---------------- P pass: 2 n-rows per thread, swizzled float4 staging ----------------
// grid (2, 16, BS), block 128. smem: bss 16KB + xs 16KB
__global__ void __launch_bounds__(128) k_pmat(const float* __restrict__ x) {
    __shared__ __align__(16) float  bss[256 * RR];   // bases slice: 256 d x 16 r
    __shared__ __align__(16) float4 xs[256 * 4];     // x tile: 256 rows x 16 d, XOR-swizzled

    const int tid = threadIdx.x;
    const int nc  = blockIdx.x;   // 0..1  (256 n each)
    const int ds  = blockIdx.y;   // 0..15 (256 d each)
    const int b   = blockIdx.z;

    // stage bases slice
    {
        const float4* s = reinterpret_cast<const float4*>(
            g_bases + ((size_t)b * DD + (size_t)ds * 256) * RR);
        float4* d4 = reinterpret_cast<float4*>(bss);
#pragma unroll
        for (int i = 0; i < 8; ++i) d4[tid + i * 128] = s[tid + i * 128];
    }

    const float* xbase = x + ((size_t)b * NN + (size_t)nc * 256) * DD + (size_t)ds * 256;
    const int srow = tid >> 2;                 // 0..31 (staging row base)
    const int sc4  = tid & 3;                  // 0..3  (float4 col)
    const int ssw  = (srow >> 1) & 3;          // store swizzle (const per thread)
    const int rsw  = (tid >> 1) & 3;           // read swizzle (rows tid and tid+128 identical)

    u64 acc0[8], acc1[8];
#pragma unroll
    for (int q = 0; q < 8; ++q) { acc0[q] = 0ull; acc1[q] = 0ull; }

    // preload tile 0: rows srow + k*32, 16-d tile -> 4 float4 per row, this thread's col sc4
    float4 pre[8];
#pragma unroll
    for (int k = 0; k < 8; ++k)
        pre[k] = *reinterpret_cast<const float4*>(xbase + (size_t)(srow + k * 32) * DD + sc4 * 4);

    __syncthreads();   // bss ready

#pragma unroll 1
    for (int t = 0; t < 16; ++t) {
        // store staged tile (STS.128, swizzled, conflict-free)
#pragma unroll
        for (int k = 0; k < 8; ++k)
            xs[(srow + k * 32) * 4 + (sc4 ^ ssw)] = pre[k];
        __syncthreads();
        // prefetch next tile (hidden under compute)
        if (t < 15) {
#pragma unroll
            for (int k = 0; k < 8; ++k)
                pre[k] = *reinterpret_cast<const float4*>(
                    xbase + (size_t)(srow + k * 32) * DD + (t + 1) * 16 + sc4 * 4);
        }
        // compute 16 d for rows tid and tid+128
#pragma unroll
        for (int j4 = 0; j4 < 4; ++j4) {
            float4 xa = xs[tid * 4 + (j4 ^ rsw)];
            float4 xc = xs[(tid + 128) * 4 + (j4 ^ rsw)];
            const float* br = &bss[(t * 16 + j4 * 4) * RR];
            fma16_2_dual(acc0, acc1, packf2(xa.x, xa.x), packf2(xc.x, xc.x), br);
            fma16_2_dual(acc0, acc1, packf2(xa.y, xa.y), packf2(xc.y, xc.y), br + RR);
            fma16_2_dual(acc0, acc1, packf2(xa.z, xa.z), packf2(xc.z, xc.z), br + 2 * RR);
            fma16_2_dual(acc0, acc1, packf2(xa.w, xa.w), packf2(xc.w, xc.w), br + 3 * RR);
        }
        __syncthreads();
    }

    float acc[16];
    unpack_acc(acc0, acc);
    const int n0 = nc * 256 + tid;
    store16(g_Ppart + (((size_t)b * NSLICE + ds) * NN + n0) * RR, acc);
    unpack_acc(acc1, acc);
    store16(g_Ppart + (((size_t)b * NSLICE + ds) * NN + n0 + 128) * RR, acc);
}

// ---------------- coef kernels (reduce partials + update + fused CtC) ----------------
__device__ __forceinline__ void coef_body(bool init) {
    __shared__ float btbs[256];
    __shared__ float smcf[128][17];
    const int tid = threadIdx.x;
    const int nc  = blockIdx.x;
    const int b   = blockIdx.y;

    if (tid < 64) {
        float4 s = make_float4(0.f, 0.f, 0.f, 0.f);
#pragma unroll
        for (int sl = 0; sl < NBTB; ++sl) {
            float4 v = *reinterpret_cast<const float4*>(
                g_btbp + ((size_t)b * NBTB + sl) * 256 + tid * 4);
            s.x += v.x; s.y += v.y; s.z += v.z; s.w += v.w;
        }
        *reinterpret_cast<float4*>(&btbs[tid * 4]) = s;
    }

    const int n = nc * 128 + tid;
    float p[16];
#pragma unroll
    for (int r = 0; r < 16; ++r) p[r] = 0.f;
#pragma unroll
    for (int sl = 0; sl < NSLICE; ++sl) {
        const float4* pp = reinterpret_cast<const float4*>(
            g_Ppart + (((size_t)b * NSLICE + sl) * NN + n) * RR);
#pragma unroll
        for (int q = 0; q < 4; ++q) {
            float4 v = pp[q];
            p[4*q+0] += v.x; p[4*q+1] += v.y; p[4*q+2] += v.z; p[4*q+3] += v.w;
        }
    }

    float cf[16];
    if (init) {
        float m = p[0];
#pragma unroll
        for (int r = 1; r < 16; ++r) m = fmaxf(m, p[r]);
        float s = 0.f;
#pragma unroll
        for (int r = 0; r < 16; ++r) { cf[r] = __expf(INVT * (p[r] - m)); s += cf[r]; }
        float inv = 1.f / s;
#pragma unroll
        for (int r = 0; r < 16; ++r) cf[r] *= inv;
    } else {
        load16(g_coef + ((size_t)b * NN + n) * RR, cf);
    }
    __syncthreads();

    float den[16];
    mat16(den, cf, btbs);
#pragma unroll
    for (int r = 0; r < 16; ++r) cf[r] = cf[r] * p[r] / (den[r] + EPSV);
    store16(g_coef + ((size_t)b * NN + n) * RR, cf);

#pragma unroll
    for (int r = 0; r < 16; ++r) smcf[tid][r] = cf[r];
    __syncthreads();
#pragma unroll
    for (int k = 0; k < 2; ++k) {
        int p2 = tid + k * 128;
        int r = p2 >> 4, s2 = p2 & 15;
        float s = 0.f;
#pragma unroll 8
        for (int i = 0; i < 128; ++i) s = fmaf(smcf[i][r], smcf[i][s2], s);
        g_ctcp[((size_t)b * NCTC + nc) * 256 + p2] = s;
    }
}
__global__ void __launch_bounds__(128) k_coef_initupd() { coef_body(true); }   // grid (4, BS)
__global__ void __launch_bounds__(128) k_coef_upd()     { coef_body(false); }  // grid (4, BS)

// ---------------- Q pass: 2 d per thread + bases update + BtB gram ----------------
// grid (16, BS), block 128. Thread owns d = dc*256 + tid*2 and d+1.
__global__ void __launch_bounds__(128) k_qmat(const float* __restrict__ x) {
    __shared__ __align__(16) float cfs[NN * RR];   // 32 KB coef (aliased for gram)
    __shared__ float ctcs[256];
    const int tid = threadIdx.x;
    const int dc  = blockIdx.x;   // 0..15
    const int b   = blockIdx.y;
    {
        const float4* s = reinterpret_cast<const float4*>(g_coef + (size_t)b * NN * RR);
        float4* dst = reinterpret_cast<float4*>(cfs);
#pragma unroll
        for (int i = 0; i < 16; ++i) dst[tid + i * 128] = s[tid + i * 128];
    }
    if (tid < 64) {
        float4 s = make_float4(0.f, 0.f, 0.f, 0.f);
#pragma unroll
        for (int sl = 0; sl < NCTC; ++sl) {
            float4 v = *reinterpret_cast<const float4*>(
                g_ctcp + ((size_t)b * NCTC + sl) * 256 + tid * 4);
            s.x += v.x; s.y += v.y; s.z += v.z; s.w += v.w;
        }
        *reinterpret_cast<float4*>(&ctcs[tid * 4]) = s;
    }

    const int d = dc * 256 + tid * 2;
    const float* xb = x + (size_t)b * NN * DD + d;

    // preload two 8-n blocks of x column-pairs (LDG.64)
    float2 xv0[8], xv1[8];
#pragma unroll
    for (int i = 0; i < 8; ++i) xv0[i] = *reinterpret_cast<const float2*>(xb + (size_t)i * DD);
#pragma unroll
    for (int i = 0; i < 8; ++i) xv1[i] = *reinterpret_cast<const float2*>(xb + (size_t)(8 + i) * DD);

    __syncthreads();

    u64 a0[8], a1[8];   // accumulators for d (r-paired) and d+1
#pragma unroll
    for (int q = 0; q < 8; ++q) { a0[q] = 0ull; a1[q] = 0ull; }

#pragma unroll 1
    for (int n0 = 0; n0 < NN; n0 += 16) {
        const bool pf = (n0 + 16) < NN;
#pragma unroll
        for (int i = 0; i < 8; ++i)
            fma16_2_dual(a0, a1, packf2(xv0[i].x, xv0[i].x), packf2(xv0[i].y, xv0[i].y),
                         &cfs[(n0 + i) * RR]);
        if (pf) {
#pragma unroll
            for (int i = 0; i < 8; ++i)
                xv0[i] = *reinterpret_cast<const float2*>(xb + (size_t)(n0 + 16 + i) * DD);
        }
#pragma unroll
        for (int i = 0; i < 8; ++i)
            fma16_2_dual(a0, a1, packf2(xv1[i].x, xv1[i].x), packf2(xv1[i].y, xv1[i].y),
                         &cfs[(n0 + 8 + i) * RR]);
        if (pf) {
#pragma unroll
            for (int i = 0; i < 8; ++i)
                xv1[i] = *reinterpret_cast<const float2*>(xb + (size_t)(n0 + 24 + i) * DD);
        }
    }

    // bases multiplicative update for rows d and d+1
    float acc[16], bs[16], den[16];
    float bs_keep[2][16];

    unpack_acc(a0, acc);
    load16(g_bases + ((size_t)b * DD + d) * RR, bs);
    mat16(den, bs, ctcs);
#pragma unroll
    for (int r = 0; r < 16; ++r) bs[r] = bs[r] * acc[r] / (den[r] + EPSV);
    store16(g_bases + ((size_t)b * DD + d) * RR, bs);
#pragma unroll
    for (int r = 0; r < 16; ++r) bs_keep[0][r] = bs[r];

    unpack_acc(a1, acc);
    load16(g_bases + ((size_t)b * DD + d + 1) * RR, bs);
    mat16(den, bs, ctcs);
#pragma unroll
    for (int r = 0; r < 16; ++r) bs[r] = bs[r] * acc[r] / (den[r] + EPSV);
    store16(g_bases + ((size_t)b * DD + d + 1) * RR, bs);
#pragma unroll
    for (int r = 0; r < 16; ++r) bs_keep[1][r] = bs[r];

    // fused BtB gram partial from NEW bases (256 rows of this block)
    __syncthreads();
    float (*smb)[17] = reinterpret_cast<float (*)[17]>(cfs);
#pragma unroll
    for (int r = 0; r < 16; ++r) {
        smb[tid * 2 + 0][r] = bs_keep[0][r];
        smb[tid * 2 + 1][r] = bs_keep[1][r];
    }
    __syncthreads();
#pragma unroll
    for (int k = 0; k < 2; ++k) {
        int p2 = tid + k * 128;
        int r = p2 >> 4, s2 = p2 & 15;
        float s = 0.f;
#pragma unroll 8
        for (int i = 0; i < 256; ++i) s = fmaf(smb[i][r], smb[i][s2], s);
        g_btbp[((size_t)b * NBTB + dc) * 256 + p2] = s;
    }
}

// ---------------- reconstruction: 2 d per thread ----------------
// grid (16, BS), block 128
__global__ void __launch_bounds__(128) k_out(float* __restrict__ out) {
    __shared__ __align__(16) float cfs[NN * RR];
    const int tid = threadIdx.x;
    const int dc  = blockIdx.x;
    const int b   = blockIdx.y;
    {
        const float4* s = reinterpret_cast<const float4*>(g_coef + (size_t)b * NN * RR);
        float4* dst = reinterpret_cast<float4*>(cfs);
#pragma unroll
        for (int i = 0; i < 16; ++i) dst[tid + i * 128] = s[tid + i * 128];
    }
    __syncthreads();

    const int d = dc * 256 + tid * 2;
    float bsv[16];
    u64 b0[8], b1[8];
    load16(g_bases + ((size_t)b * DD + d) * RR, bsv);
#pragma unroll
    for (int q = 0; q < 8; ++q) b0[q] = packf2(bsv[2*q], bsv[2*q+1]);
    load16(g_bases + ((size_t)b * DD + d + 1) * RR, bsv);
#pragma unroll
    for (int q = 0; q < 8; ++q) b1[q] = packf2(bsv[2*q], bsv[2*q+1]);

    float* ob = out + (size_t)b * NN * DD + d;
#pragma unroll 2
    for (int n = 0; n < NN; ++n) {
        const ulonglong2* c2 = reinterpret_cast<const ulonglong2*>(&cfs[n * RR]);
        u64 s0a = 0ull, s0b = 0ull, s1a = 0ull, s1b = 0ull;
#pragma unroll
        for (int q = 0; q < 4; ++q) {
            ulonglong2 pq = c2[q];
            ffma2(s0a, b0[2*q+0], pq.x);
            ffma2(s0b, b0[2*q+1], pq.y);
            ffma2(s1a, b1[2*q+0], pq.x);
            ffma2(s1b, b1[2*q+1], pq.y);
        }
        float u0, u1, v0, v1, w0, w1, z0, z1;
        unpackf2(s0a, u0, u1); unpackf2(s0b, v0, v1);
        unpackf2(s1a, w0, w1); unpackf2(s1b, z0, z1);
        float2 o;
        o.x = (u0 + u1) + (v0 + v1);
        o.y = (w0 + w1) + (z0 + z1);
        *reinterpret_cast<float2*>(ob + (size_t)n * DD) = o;
    }
}

// ---------------- launch ----------------
extern "C" void kernel_launch(void* const* d_in, const int* in_sizes, int n_in,
                              void* d_out, int out_size) {
    (void)in_sizes; (void)n_in; (void)out_size;
    const float* x     = (const float*)d_in[0];
    const float* bases = (const float*)d_in[1];
    float* out = (float*)d_out;

    k_copy_bases<<<(BS * DD * RR / 4) / 256, 256>>>(bases);
    k_btb0<<<dim3(NBTB, BS), 256>>>(bases);

    k_pmat<<<dim3(2, 16, BS), 128>>>(x);
    k_coef_initupd<<<dim3(4, BS), 128>>>();

    for (int it = 0; it < 7; ++it) {
        k_qmat<<<dim3(16, BS), 128>>>(x);        // bases update + BtB gram
        k_pmat<<<dim3(2, 16, BS), 128>>>(x);
        k_coef_upd<<<dim3(4, BS), 128>>>();      // coef update + CtC gram
    }

    k_out<<<dim3(16, BS), 128>>>(out);
}

// round 9
// speedup vs baseline: 1.3080x; 1.0020x over previous
#include <cuda_runtime.h>

#define BS   16
#define DD   4096
#define NN   512
#define RR   16
#define EPSV 1e-6f
#define INVT 100.0f

#define NSLICE 16     // P partial slices (256 d each)
#define NBTB   16     // BtB partials (one per pmat ds-slice, nc==0)
#define NCTC   16     // CtC partials (one per coef block)
#define NSPL   2      // qmat n-split

typedef unsigned long long u64;

// ---------------- scratch ----------------
__device__ float g_b0[BS * DD * RR];               // bases ping
__device__ float g_b1[BS * DD * RR];               // bases pong
__device__ float g_coef [BS * NN * RR];
__device__ float g_Ppart[BS * NSLICE * NN * RR];   // 8 MB
__device__ float g_Qpart[BS * NSPL * DD * RR];     // 8 MB
__device__ float g_btbp [BS * NBTB * 256];
__device__ float g_ctcp [BS * NCTC * 256];

// ---------------- packed f32x2 ----------------
__device__ __forceinline__ void ffma2(u64& acc, u64 a, u64 b) {
    asm("fma.rn.f32x2 %0, %1, %2, %3;" : "=l"(acc) : "l"(a), "l"(b), "l"(acc));
}
__device__ __forceinline__ u64 packf2(float lo, float hi) {
    u64 r; asm("mov.b64 %0, {%1, %2};" : "=l"(r) : "f"(lo), "f"(hi)); return r;
}
__device__ __forceinline__ void unpackf2(u64 v, float& lo, float& hi) {
    asm("mov.b64 {%0, %1}, %2;" : "=f"(lo), "=f"(hi) : "l"(v));
}
__device__ __forceinline__ void fma16_2_dual(u64* a0, u64* a1, u64 x0, u64 x1,
                                             const float* __restrict__ row) {
    const ulonglong2* r2 = reinterpret_cast<const ulonglong2*>(row);
#pragma unroll
    for (int q = 0; q < 4; ++q) {
        ulonglong2 p = r2[q];
        ffma2(a0[2*q+0], x0, p.x);
        ffma2(a0[2*q+1], x0, p.y);
        ffma2(a1[2*q+0], x1, p.x);
        ffma2(a1[2*q+1], x1, p.y);
    }
}
__device__ __forceinline__ void unpack_acc(const u64* acc2, float* v) {
#pragma unroll
    for (int q = 0; q < 8; ++q) unpackf2(acc2[q], v[2*q], v[2*q+1]);
}

// ---------------- helpers ----------------
__device__ __forceinline__ void load16(const float* __restrict__ src, float* v) {
    const float4* s4 = reinterpret_cast<const float4*>(src);
#pragma unroll
    for (int q = 0; q < 4; ++q) {
        float4 t = s4[q];
        v[4*q+0] = t.x; v[4*q+1] = t.y; v[4*q+2] = t.z; v[4*q+3] = t.w;
    }
}
__device__ __forceinline__ void store16(float* __restrict__ dst, const float* v) {
    float4* d4 = reinterpret_cast<float4*>(dst);
#pragma unroll
    for (int q = 0; q < 4; ++q)
        d4[q] = make_float4(v[4*q+0], v[4*q+1], v[4*q+2], v[4*q+3]);
}
__device__ __forceinline__ void mat16(float* den, const float* v, const float* __restrict__ G) {
#pragma unroll
    for (int s2 = 0; s2 < 16; ++s2) den[s2] = 0.f;
#pragma unroll
    for (int r = 0; r < 16; ++r) {
        float c = v[r];
        const float* row = &G[r * 16];
#pragma unroll
        for (int s2 = 0; s2 < 16; ++s2) den[s2] = fmaf(c, row[s2], den[s2]);
    }
}

// ---------------- P pass (+ inline bases update + BtB gram) ----------------
// grid (2, 16, BS), block 128. bss 16KB + xs 16KB + ctcs 1KB.
// If UPD: new_bases = old * Q/(old@CtC+eps) computed into bss (and written by nc==0),
// then P computed against the NEW bases.
template <bool UPD>
__global__ void __launch_bounds__(128) k_pmat(const float* __restrict__ x,
                                              const float* __restrict__ bold,
                                              float* __restrict__ bnew) {
    __shared__ __align__(16) float  bss[256 * RR];   // bases slice (new if UPD)
    __shared__ __align__(16) float4 xs[256 * 4];     // x tile 256 n x 16 d, swizzled
    __shared__ float ctcs[256];

    const int tid = threadIdx.x;
    const int nc  = blockIdx.x;   // 0..1  (256 n each)
    const int ds  = blockIdx.y;   // 0..15 (256 d each)
    const int b   = blockIdx.z;

    if (UPD) {
        if (tid < 64) {
            float4 s = make_float4(0.f, 0.f, 0.f, 0.f);
#pragma unroll
            for (int sl = 0; sl < NCTC; ++sl) {
                float4 v = *reinterpret_cast<const float4*>(
                    g_ctcp + ((size_t)b * NCTC + sl) * 256 + tid * 4);
                s.x += v.x; s.y += v.y; s.z += v.z; s.w += v.w;
            }
            *reinterpret_cast<float4*>(&ctcs[tid * 4]) = s;
        }
        __syncthreads();
        // update 2 rows per thread
#pragma unroll
        for (int rr = 0; rr < 2; ++rr) {
            const int ld = tid * 2 + rr;
            const int gd = ds * 256 + ld;
            float ob[16], q[16], den[16];
            load16(bold + ((size_t)b * DD + gd) * RR, ob);
            load16(g_Qpart + (((size_t)b * NSPL + 0) * DD + gd) * RR, q);
            {
                float q1[16];
                load16(g_Qpart + (((size_t)b * NSPL + 1) * DD + gd) * RR, q1);
#pragma unroll
                for (int r = 0; r < 16; ++r) q[r] += q1[r];
            }
            mat16(den, ob, ctcs);
#pragma unroll
            for (int r = 0; r < 16; ++r) ob[r] = ob[r] * q[r] / (den[r] + EPSV);
#pragma unroll
            for (int r = 0; r < 16; ++r) bss[ld * RR + r] = ob[r];
            if (nc == 0) store16(bnew + ((size_t)b * DD + gd) * RR, ob);
        }
    } else {
        const float4* s = reinterpret_cast<const float4*>(
            bold + ((size_t)b * DD + (size_t)ds * 256) * RR);
        float4* d4 = reinterpret_cast<float4*>(bss);
#pragma unroll
        for (int i = 0; i < 8; ++i) d4[tid + i * 128] = s[tid + i * 128];
    }

    const float* xbase = x + ((size_t)b * NN + (size_t)nc * 256) * DD + (size_t)ds * 256;
    const int srow = tid >> 2;
    const int sc4  = tid & 3;
    const int ssw  = (srow >> 1) & 3;
    const int rsw  = (tid >> 1) & 3;

    u64 acc0[8], acc1[8];
#pragma unroll
    for (int q = 0; q < 8; ++q) { acc0[q] = 0ull; acc1[q] = 0ull; }

    float4 pre[8];
#pragma unroll
    for (int k = 0; k < 8; ++k)
        pre[k] = *reinterpret_cast<const float4*>(xbase + (size_t)(srow + k * 32) * DD + sc4 * 4);

    __syncthreads();   // bss ready

#pragma unroll 1
    for (int t = 0; t < 16; ++t) {
#pragma unroll
        for (int k = 0; k < 8; ++k)
            xs[(srow + k * 32) * 4 + (sc4 ^ ssw)] = pre[k];
        __syncthreads();
        if (t < 15) {
#pragma unroll
            for (int k = 0; k < 8; ++k)
                pre[k] = *reinterpret_cast<const float4*>(
                    xbase + (size_t)(srow + k * 32) * DD + (t + 1) * 16 + sc4 * 4);
        }
#pragma unroll
        for (int j4 = 0; j4 < 4; ++j4) {
            float4 xa = xs[tid * 4 + (j4 ^ rsw)];
            float4 xc = xs[(tid + 128) * 4 + (j4 ^ rsw)];
            const float* br = &bss[(t * 16 + j4 * 4) * RR];
            fma16_2_dual(acc0, acc1, packf2(xa.x, xa.x), packf2(xc.x, xc.x), br);
            fma16_2_dual(acc0, acc1, packf2(xa.y, xa.y), packf2(xc.y, xc.y), br + RR);
            fma16_2_dual(acc0, acc1, packf2(xa.z, xa.z), packf2(xc.z, xc.z), br + 2 * RR);
            fma16_2_dual(acc0, acc1, packf2(xa.w, xa.w), packf2(xc.w, xc.w), br + 3 * RR);
        }
        __syncthreads();
    }

    float acc[16];
    unpack_acc(acc0, acc);
    const int n0 = nc * 256 + tid;
    store16(g_Ppart + (((size_t)b * NSLICE + ds) * NN + n0) * RR, acc);
    unpack_acc(acc1, acc);
    store16(g_Ppart + (((size_t)b * NSLICE + ds) * NN + n0 + 128) * RR, acc);

    // BtB gram partial from the bases in bss (new if UPD, initial otherwise)
    if (nc == 0) {
#pragma unroll
        for (int k = 0; k < 2; ++k) {
            int p2 = tid + k * 128;
            int r = p2 >> 4, s2 = p2 & 15;
            float s0 = 0.f, s1 = 0.f, s2a = 0.f, s3 = 0.f;
#pragma unroll 4
            for (int i = 0; i < 256; i += 4) {
                s0  = fmaf(bss[(i+0)*16 + r], bss[(i+0)*16 + s2], s0);
                s1  = fmaf(bss[(i+1)*16 + r], bss[(i+1)*16 + s2], s1);
                s2a = fmaf(bss[(i+2)*16 + r], bss[(i+2)*16 + s2], s2a);
                s3  = fmaf(bss[(i+3)*16 + r], bss[(i+3)*16 + s2], s3);
            }
            g_btbp[((size_t)b * NBTB + ds) * 256 + p2] = (s0 + s1) + (s2a + s3);
        }
    }
}

// ---------------- coef kernel: 32 n per block, 4-way parallel gather ----------------
// grid (16, BS), block 128
__device__ __forceinline__ void coef_body(bool init) {
    __shared__ float btbs[256];
    __shared__ __align__(16) float pg[4][32][16];    // 8KB slice-group partials
    __shared__ float smcf[32][17];
    const int tid = threadIdx.x;
    const int nc  = blockIdx.x;     // 0..15 (32 n each)
    const int b   = blockIdx.y;

    if (tid < 64) {
        float4 s = make_float4(0.f, 0.f, 0.f, 0.f);
#pragma unroll
        for (int sl = 0; sl < NBTB; ++sl) {
            float4 v = *reinterpret_cast<const float4*>(
                g_btbp + ((size_t)b * NBTB + sl) * 256 + tid * 4);
            s.x += v.x; s.y += v.y; s.z += v.z; s.w += v.w;
        }
        *reinterpret_cast<float4*>(&btbs[tid * 4]) = s;
    }

    const int nl = tid & 31;
    const int g  = tid >> 5;        // slice group 0..3
    const int n  = nc * 32 + nl;
    {
        float p[16];
#pragma unroll
        for (int r = 0; r < 16; ++r) p[r] = 0.f;
#pragma unroll
        for (int k = 0; k < 4; ++k) {
            const float4* pp = reinterpret_cast<const float4*>(
                g_Ppart + (((size_t)b * NSLICE + g * 4 + k) * NN + n) * RR);
#pragma unroll
            for (int q = 0; q < 4; ++q) {
                float4 v = pp[q];
                p[4*q+0] += v.x; p[4*q+1] += v.y; p[4*q+2] += v.z; p[4*q+3] += v.w;
            }
        }
        store16(&pg[g][nl][0], p);
    }
    __syncthreads();

    if (tid < 32) {
        float p[16];
#pragma unroll
        for (int r = 0; r < 16; ++r)
            p[r] = (pg[0][tid][r] + pg[1][tid][r]) + (pg[2][tid][r] + pg[3][tid][r]);

        const int nn = nc * 32 + tid;
        float cf[16];
        if (init) {
            float m = p[0];
#pragma unroll
            for (int r = 1; r < 16; ++r) m = fmaxf(m, p[r]);
            float s = 0.f;
#pragma unroll
            for (int r = 0; r < 16; ++r) { cf[r] = __expf(INVT * (p[r] - m)); s += cf[r]; }
            float inv = 1.f / s;
#pragma unroll
            for (int r = 0; r < 16; ++r) cf[r] *= inv;
        } else {
            load16(g_coef + ((size_t)b * NN + nn) * RR, cf);
        }
        float den[16];
        mat16(den, cf, btbs);
#pragma unroll
        for (int r = 0; r < 16; ++r) cf[r] = cf[r] * p[r] / (den[r] + EPSV);
        store16(g_coef + ((size_t)b * NN + nn) * RR, cf);
#pragma unroll
        for (int r = 0; r < 16; ++r) smcf[tid][r] = cf[r];
    }
    __syncthreads();

    // CtC partial over this block's 32 coef rows
#pragma unroll
    for (int k = 0; k < 2; ++k) {
        int p2 = tid + k * 128;
        int r = p2 >> 4, s2 = p2 & 15;
        float s0 = 0.f, s1 = 0.f;
#pragma unroll
        for (int i = 0; i < 32; i += 2) {
            s0 = fmaf(smcf[i][r],   smcf[i][s2],   s0);
            s1 = fmaf(smcf[i+1][r], smcf[i+1][s2], s1);
        }
        g_ctcp[((size_t)b * NCTC + nc) * 256 + p2] = s0 + s1;
    }
}
__global__ void __launch_bounds__(128) k_coef_initupd() { coef_body(true); }
__global__ void __launch_bounds__(128) k_coef_upd()     { coef_body(false); }

// ---------------- Q pass: pure partial GEMM, split n 2 ways ----------------
// grid (16, 2, BS), block 128, 2 d per thread
__global__ void __launch_bounds__(128) k_qmat(const float* __restrict__ x) {
    __shared__ __align__(16) float cfs[256 * RR];   // 16KB coef half
    const int tid = threadIdx.x;
    const int dc  = blockIdx.x;   // 0..15 (256 d)
    const int h   = blockIdx.y;   // 0..1  (256 n)
    const int b   = blockIdx.z;
    {
        const float4* s = reinterpret_cast<const float4*>(
            g_coef + ((size_t)b * NN + (size_t)h * 256) * RR);
        float4* dst = reinterpret_cast<float4*>(cfs);
#pragma unroll
        for (int i = 0; i < 8; ++i) dst[tid + i * 128] = s[tid + i * 128];
    }

    const int d = dc * 256 + tid * 2;
    const float* xb = x + ((size_t)b * NN + (size_t)h * 256) * DD + d;

    float2 xv0[8], xv1[8];
#pragma unroll
    for (int i = 0; i < 8; ++i) xv0[i] = *reinterpret_cast<const float2*>(xb + (size_t)i * DD);
#pragma unroll
    for (int i = 0; i < 8; ++i) xv1[i] = *reinterpret_cast<const float2*>(xb + (size_t)(8 + i) * DD);

    __syncthreads();

    u64 a0[8], a1[8];
#pragma unroll
    for (int q = 0; q < 8; ++q) { a0[q] = 0ull; a1[q] = 0ull; }

#pragma unroll 1
    for (int n0 = 0; n0 < 256; n0 += 16) {
        const bool pf = (n0 + 16) < 256;
#pragma unroll
        for (int i = 0; i < 8; ++i)
            fma16_2_dual(a0, a1, packf2(xv0[i].x, xv0[i].x), packf2(xv0[i].y, xv0[i].y),
                         &cfs[(n0 + i) * RR]);
        if (pf) {
#pragma unroll
            for (int i = 0; i < 8; ++i)
                xv0[i] = *reinterpret_cast<const float2*>(xb + (size_t)(n0 + 16 + i) * DD);
        }
#pragma unroll
        for (int i = 0; i < 8; ++i)
            fma16_2_dual(a0, a1, packf2(xv1[i].x, xv1[i].x), packf2(xv1[i].y, xv1[i].y),
                         &cfs[(n0 + 8 + i) * RR]);
        if (pf) {
#pragma unroll
            for (int i = 0; i < 8; ++i)
                xv1[i] = *reinterpret_cast<const float2*>(xb + (size_t)(n0 + 24 + i) * DD);
        }
    }

    float acc[16];
    unpack_acc(a0, acc);
    store16(g_Qpart + (((size_t)b * NSPL + h) * DD + d) * RR, acc);
    unpack_acc(a1, acc);
    store16(g_Qpart + (((size_t)b * NSPL + h) * DD + d + 1) * RR, acc);
}

// ---------------- reconstruction: 2 d per thread ----------------
// grid (16, BS), block 128
__global__ void __launch_bounds__(128) k_out(const float* __restrict__ bfin,
                                             float* __restrict__ out) {
    __shared__ __align__(16) float cfs[NN * RR];
    const int tid = threadIdx.x;
    const int dc  = blockIdx.x;
    const int b   = blockIdx.y;
    {
        const float4* s = reinterpret_cast<const float4*>(g_coef + (size_t)b * NN * RR);
        float4* dst = reinterpret_cast<float4*>(cfs);
#pragma unroll
        for (int i = 0; i < 16; ++i) dst[tid + i * 128] = s[tid + i * 128];
    }
    __syncthreads();

    const int d = dc * 256 + tid * 2;
    float bsv[16];
    u64 b0[8], b1[8];
    load16(bfin + ((size_t)b * DD + d) * RR, bsv);
#pragma unroll
    for (int q = 0; q < 8; ++q) b0[q] = packf2(bsv[2*q], bsv[2*q+1]);
    load16(bfin + ((size_t)b * DD + d + 1) * RR, bsv);
#pragma unroll
    for (int q = 0; q < 8; ++q) b1[q] = packf2(bsv[2*q], bsv[2*q+1]);

    float* ob = out + (size_t)b * NN * DD + d;
#pragma unroll 2
    for (int n = 0; n < NN; ++n) {
        const ulonglong2* c2 = reinterpret_cast<const ulonglong2*>(&cfs[n * RR]);
        u64 s0a = 0ull, s0b = 0ull, s1a = 0ull, s1b = 0ull;
#pragma unroll
        for (int q = 0; q < 4; ++q) {
            ulonglong2 pq = c2[q];
            ffma2(s0a, b0[2*q+0], pq.x);
            ffma2(s0b, b0[2*q+1], pq.y);
            ffma2(s1a, b1[2*q+0], pq.x);
            ffma2(s1b, b1[2*q+1], pq.y);
        }
        float u0, u1, v0, v1, w0, w1, z0, z1;
        unpackf2(s0a, u0, u1); unpackf2(s0b, v0, v1);
        unpackf2(s1a, w0, w1); unpackf2(s1b, z0, z1);
        float2 o;
        o.x = (u0 + u1) + (v0 + v1);
        o.y = (w0 + w1) + (z0 + z1);
        *reinterpret_cast<float2*>(ob + (size_t)n * DD) = o;
    }
}

// ---------------- launch ----------------
extern "C" void kernel_launch(void* const* d_in, const int* in_sizes, int n_in,
                              void* d_out, int out_size) {
    (void)in_sizes; (void)n_in; (void)out_size;
    const float* x     = (const float*)d_in[0];
    const float* bases = (const float*)d_in[1];
    float* out = (float*)d_out;

    float* b0p; cudaGetSymbolAddress((void**)&b0p, g_b0);
    float* b1p; cudaGetSymbolAddress((void**)&b1p, g_b1);

    // P(X, bases0) + BtB(bases0), then softmax init + coef update #1
    k_pmat<false><<<dim3(2, 16, BS), 128>>>(x, bases, nullptr);
    k_coef_initupd<<<dim3(16, BS), 128>>>();

    const float* boldp = bases;
    float* bnewp = b0p;
    for (int it = 0; it < 7; ++it) {
        k_qmat<<<dim3(16, NSPL, BS), 128>>>(x);                     // Q partials
        k_pmat<true><<<dim3(2, 16, BS), 128>>>(x, boldp, bnewp);    // bases upd + P + BtB
        k_coef_upd<<<dim3(16, BS), 128>>>();                        // coef upd + CtC
        boldp = bnewp;
        bnewp = (bnewp == b0p) ? b1p : b0p;
    }

    k_out<<<dim3(16, BS), 128>>>(boldp, out);
}